// round 10
// baseline (speedup 1.0000x reference)
#include <cuda_runtime.h>
#include <cstdint>

#define BB 4
#define CC 256
#define HH 56
#define WW 56
#define CR 64          // C / 4
#define GG 16          // groups
#define GC 16
#define KK 7
#define K2T 49
#define M2 784         // GG * K2T
#define HW 3136        // HH * WW
#define PAD 3
#define N1 (BB * CR * HW)   // 802816

// K3 smem partition (floats)
#define XS_FLOATS (GC * 10 * 64)          // 10240 (40KB)
#define WS_FLOATS (K2T * 224)             // 10976 (43.9KB)
#define K3_SMEM_BYTES ((XS_FLOATS + WS_FLOATS) * 4)   // 84864

// Scratch (__device__ globals; no allocations allowed)
__device__ float g_p[2 * N1];               // K1 split-K partials
__device__ float g_w1[N1];                  // [B, Cr, HW]
__device__ float g_w2[BB * M2 * HW];        // [B, G*49, HW]

// ---------------------------------------------------------------------------
// K1a: partial conv1 over half the C range (split-K = 2). (round-8, unchanged)
// ---------------------------------------------------------------------------
__global__ __launch_bounds__(128) void k1a_partial(
        const float* __restrict__ x,
        const float* __restrict__ w1w) {
    __shared__ float As[64 * 68];    // [k][o]
    __shared__ float Bs[64 * 32];    // [k][px]

    const int tid = threadIdx.x;
    const int tx = tid & 7;
    const int ty = tid >> 3;
    const int px0 = blockIdx.x * 32;
    const int b = blockIdx.y;
    const int ks = blockIdx.z;

    float acc[4][4];
#pragma unroll
    for (int i = 0; i < 4; ++i)
#pragma unroll
        for (int u = 0; u < 4; ++u) acc[i][u] = 0.f;

    for (int kt = ks * 128; kt < ks * 128 + 128; kt += 64) {
        {
            int k = tid & 63;
            int oh = tid >> 6;
#pragma unroll
            for (int r = 0; r < 32; ++r) {
                int o = 2 * r + oh;
                As[k * 68 + o] = w1w[o * CC + kt + k];
            }
        }
        {
            int j = tid & 31;
            int kh = tid >> 5;
#pragma unroll
            for (int r = 0; r < 16; ++r) {
                int k = 4 * r + kh;
                Bs[k * 32 + j] = x[(size_t)(b * CC + kt + k) * HW + px0 + j];
            }
        }
        __syncthreads();

#pragma unroll 16
        for (int k = 0; k < 64; ++k) {
            float4 av = *(const float4*)&As[k * 68 + ty * 4];
            float4 bv = *(const float4*)&Bs[k * 32 + tx * 4];
            acc[0][0] = fmaf(av.x, bv.x, acc[0][0]);
            acc[0][1] = fmaf(av.x, bv.y, acc[0][1]);
            acc[0][2] = fmaf(av.x, bv.z, acc[0][2]);
            acc[0][3] = fmaf(av.x, bv.w, acc[0][3]);
            acc[1][0] = fmaf(av.y, bv.x, acc[1][0]);
            acc[1][1] = fmaf(av.y, bv.y, acc[1][1]);
            acc[1][2] = fmaf(av.y, bv.z, acc[1][2]);
            acc[1][3] = fmaf(av.y, bv.w, acc[1][3]);
            acc[2][0] = fmaf(av.z, bv.x, acc[2][0]);
            acc[2][1] = fmaf(av.z, bv.y, acc[2][1]);
            acc[2][2] = fmaf(av.z, bv.z, acc[2][2]);
            acc[2][3] = fmaf(av.z, bv.w, acc[2][3]);
            acc[3][0] = fmaf(av.w, bv.x, acc[3][0]);
            acc[3][1] = fmaf(av.w, bv.y, acc[3][1]);
            acc[3][2] = fmaf(av.w, bv.z, acc[3][2]);
            acc[3][3] = fmaf(av.w, bv.w, acc[3][3]);
        }
        __syncthreads();
    }

#pragma unroll
    for (int i = 0; i < 4; ++i) {
        int o = ty * 4 + i;
        float4 v = make_float4(acc[i][0], acc[i][1], acc[i][2], acc[i][3]);
        *(float4*)(g_p + (size_t)ks * N1 + (size_t)(b * CR + o) * HW
                   + px0 + tx * 4) = v;
    }
}

// ---------------------------------------------------------------------------
// K1b: sum partials + BN(eval) + ReLU. (round-8, unchanged)
// ---------------------------------------------------------------------------
__global__ __launch_bounds__(256) void k1b_bn_relu(
        const float* __restrict__ gamma,
        const float* __restrict__ beta,
        const float* __restrict__ mean,
        const float* __restrict__ var) {
    int i4 = blockIdx.x * blockDim.x + threadIdx.x;
    if (i4 >= N1 / 4) return;
    int idx = i4 * 4;
    int o = (idx / HW) % CR;

    float sc = gamma[o] * rsqrtf(var[o] + 1e-5f);
    float sh = beta[o] - mean[o] * sc;

    float4 p0 = *(const float4*)(g_p + idx);
    float4 p1 = *(const float4*)(g_p + N1 + idx);
    float4 v;
    v.x = fmaxf(fmaf(p0.x + p1.x, sc, sh), 0.f);
    v.y = fmaxf(fmaf(p0.y + p1.y, sc, sh), 0.f);
    v.z = fmaxf(fmaf(p0.z + p1.z, sc, sh), 0.f);
    v.w = fmaxf(fmaf(p0.w + p1.w, sc, sh), 0.f);
    *(float4*)(g_w1 + idx) = v;
}

// ---------------------------------------------------------------------------
// K2: w2 = conv2_1x1(w1) + bias. Tile 64o x 64px, 128 thr, 8x4. (round-8)
// ---------------------------------------------------------------------------
__global__ __launch_bounds__(128) void k2_conv2(
        const float* __restrict__ w2w,
        const float* __restrict__ w2b) {
    __shared__ float As[64 * 68];
    __shared__ float Bs[64 * 64];

    const int tid = threadIdx.x;
    const int tx = tid & 15;
    const int ty = tid >> 4;
    const int px0 = blockIdx.x * 64;
    const int o0 = blockIdx.y * 64;
    const int b = blockIdx.z;

    {
        int k = tid & 63;
        int oh = tid >> 6;
#pragma unroll
        for (int r = 0; r < 32; ++r) {
            int o = 2 * r + oh;
            As[k * 68 + o] = (o0 + o < M2) ? w2w[(o0 + o) * CR + k] : 0.f;
        }
    }
    {
        int j = tid & 63;
        int kh = tid >> 6;
#pragma unroll
        for (int r = 0; r < 32; ++r) {
            int k = 2 * r + kh;
            Bs[k * 64 + j] = g_w1[(size_t)(b * CR + k) * HW + px0 + j];
        }
    }
    __syncthreads();

    float acc[8][4];
#pragma unroll
    for (int i = 0; i < 8; ++i)
#pragma unroll
        for (int u = 0; u < 4; ++u) acc[i][u] = 0.f;

#pragma unroll 8
    for (int k = 0; k < 64; ++k) {
        float4 a0 = *(const float4*)&As[k * 68 + ty * 8];
        float4 a1 = *(const float4*)&As[k * 68 + ty * 8 + 4];
        float4 bv = *(const float4*)&Bs[k * 64 + tx * 4];
        float av[8] = {a0.x, a0.y, a0.z, a0.w, a1.x, a1.y, a1.z, a1.w};
#pragma unroll
        for (int i = 0; i < 8; ++i) {
            acc[i][0] = fmaf(av[i], bv.x, acc[i][0]);
            acc[i][1] = fmaf(av[i], bv.y, acc[i][1]);
            acc[i][2] = fmaf(av[i], bv.z, acc[i][2]);
            acc[i][3] = fmaf(av[i], bv.w, acc[i][3]);
        }
    }

#pragma unroll
    for (int i = 0; i < 8; ++i) {
        int o = o0 + ty * 8 + i;
        if (o >= M2) continue;
        float bias = w2b[o];
        float4 v;
        v.x = acc[i][0] + bias;
        v.y = acc[i][1] + bias;
        v.z = acc[i][2] + bias;
        v.w = acc[i][3] + bias;
        *(float4*)(g_w2 + (size_t)(b * M2 + o) * HW + px0 + tx * 4) = v;
    }
}

// ---------------------------------------------------------------------------
// K3: involution reduce. Block = (4-row band, group, batch); 224 threads.
// Thread = 4 px x 4 ch. NEW: weight tile staged in shared memory via
// perfectly-coalesced bulk loads (each w2 element read once chip-wide);
// hot loop reads weights via LDS instead of per-thread LDG.
// ---------------------------------------------------------------------------
__global__ __launch_bounds__(224) void k3_involution(
        const float* __restrict__ x,
        float* __restrict__ out) {
    extern __shared__ float smf[];
    float* xs = smf;                  // [16ch][10rows][64]  (40KB)
    float* ws = smf + XS_FLOATS;      // [49 taps][224 px]   (43.9KB)

    const int tid = threadIdx.x;
    const int h0 = blockIdx.x * 4;
    const int g = blockIdx.y;
    const int b = blockIdx.z;

    // stage x: rows h0-3 .. h0+6, cols -3..60 (clipped)
    const float* xg = x + (size_t)(b * CC + g * GC) * HW;
    for (int i = tid; i < XS_FLOATS; i += 224) {
        int ch = i / 640;
        int rem = i - ch * 640;
        int rr = rem >> 6;
        int c = rem & 63;
        int hh = h0 - 3 + rr;
        int ww = c - 3;
        float v = 0.f;
        if (hh >= 0 && hh < HH && ww >= 0 && ww < WW)
            v = xg[(size_t)ch * HW + hh * WW + ww];
        xs[i] = v;
    }

    // stage weights: 49 taps x 224 px (4 rows x 56), contiguous per tap.
    {
        const float* wsrc = g_w2 + ((size_t)(b * GG + g) * K2T) * HW + h0 * WW;
        for (int i = tid; i < K2T * 56; i += 224) {   // float4 granularity
            int tap = i / 56;
            int j = i - tap * 56;
            float4 v = *(const float4*)(wsrc + (size_t)tap * HW + j * 4);
            *(float4*)(ws + tap * 224 + j * 4) = v;
        }
    }
    __syncthreads();

    const int q = tid % 14;
    const int cg = (tid / 14) & 3;
    const int r = tid / 56;
    const int w0 = q * 4;

    float acc[4][4];
#pragma unroll
    for (int c = 0; c < 4; ++c)
#pragma unroll
        for (int p = 0; p < 4; ++p) acc[c][p] = 0.f;

    const float* wrow = ws + r * 56 + w0;   // within-tap pixel offset

#pragma unroll
    for (int ki = 0; ki < KK; ++ki) {
        float4 wv[7];
#pragma unroll
        for (int kj = 0; kj < KK; ++kj)
            wv[kj] = *(const float4*)(wrow + (ki * KK + kj) * 224);
#pragma unroll
        for (int c = 0; c < 4; ++c) {
            const float* xr = &xs[(cg * 4 + c) * 640 + (r + ki) * 64 + w0];
            float4 xa = *(const float4*)(xr);
            float4 xb = *(const float4*)(xr + 4);
            float4 xc = *(const float4*)(xr + 8);
            float xw[12] = {xa.x, xa.y, xa.z, xa.w,
                            xb.x, xb.y, xb.z, xb.w,
                            xc.x, xc.y, xc.z, xc.w};
#pragma unroll
            for (int kj = 0; kj < KK; ++kj) {
                acc[c][0] = fmaf(wv[kj].x, xw[kj + 0], acc[c][0]);
                acc[c][1] = fmaf(wv[kj].y, xw[kj + 1], acc[c][1]);
                acc[c][2] = fmaf(wv[kj].z, xw[kj + 2], acc[c][2]);
                acc[c][3] = fmaf(wv[kj].w, xw[kj + 3], acc[c][3]);
            }
        }
    }

    const int h = h0 + r;
#pragma unroll
    for (int c = 0; c < 4; ++c) {
        float4 v = make_float4(acc[c][0], acc[c][1], acc[c][2], acc[c][3]);
        *(float4*)(out + (size_t)(b * CC + g * GC + cg * 4 + c) * HW
                   + h * WW + w0) = v;
    }
}

// ---------------------------------------------------------------------------
extern "C" void kernel_launch(void* const* d_in, const int* in_sizes, int n_in,
                              void* d_out, int out_size) {
    const float* x     = (const float*)d_in[0];
    const float* w1w   = (const float*)d_in[1];
    const float* gamma = (const float*)d_in[2];
    const float* beta  = (const float*)d_in[3];
    const float* mean  = (const float*)d_in[4];
    const float* var   = (const float*)d_in[5];
    const float* w2w   = (const float*)d_in[6];
    const float* w2b   = (const float*)d_in[7];
    float* out = (float*)d_out;

    static bool attr_set = false;
    if (!attr_set) {
        cudaFuncSetAttribute(k3_involution,
                             cudaFuncAttributeMaxDynamicSharedMemorySize,
                             K3_SMEM_BYTES);
        attr_set = true;
    }

    dim3 g1(HW / 32, BB, 2);                    // 98 x 4 x 2 = 784
    k1a_partial<<<g1, 128>>>(x, w1w);

    k1b_bn_relu<<<(N1 / 4 + 255) / 256, 256>>>(gamma, beta, mean, var);

    dim3 g2(HW / 64, (M2 + 63) / 64, BB);       // 49 x 13 x 4 = 2548
    k2_conv2<<<g2, 128>>>(w2w, w2b);

    dim3 g3(HH / 4, GG, BB);                    // 14 x 16 x 4 = 896
    k3_involution<<<g3, 224, K3_SMEM_BYTES>>>(x, out);
}

// round 11
// speedup vs baseline: 1.1731x; 1.1731x over previous
#include <cuda_runtime.h>
#include <cstdint>

#define BB 4
#define CC 256
#define HH 56
#define WW 56
#define CR 64          // C / 4
#define GG 16          // groups
#define GC 16
#define KK 7
#define K2T 49
#define M2 784         // GG * K2T
#define HW 3136        // HH * WW
#define PAD 3
#define N1 (BB * CR * HW)   // 802816

// K3 smem partition (floats)
#define XS_FLOATS (GC * 10 * 64)          // 10240 (40KB)
#define WROW_FLOATS (KK * 224)            // 1568 per stage (6.27KB)
#define K3_SMEM_BYTES ((XS_FLOATS + 2 * WROW_FLOATS) * 4)   // 53504

// Scratch (__device__ globals; no allocations allowed)
__device__ float g_p[2 * N1];               // K1 split-K partials
__device__ float g_w1[N1];                  // [B, Cr, HW]
__device__ float g_w2[BB * M2 * HW];        // [B, G*49, HW]

// ---- cp.async helpers (Ampere+ base feature, no 'a' gate) ------------------
__device__ __forceinline__ uint32_t smem_u32(const void* p) {
    uint32_t a;
    asm("{ .reg .u64 t; cvta.to.shared.u64 t, %1; cvt.u32.u64 %0, t; }"
        : "=r"(a) : "l"(p));
    return a;
}
__device__ __forceinline__ void cp_async16(uint32_t dst, const void* src) {
    asm volatile("cp.async.cg.shared.global [%0], [%1], 16;"
                 :: "r"(dst), "l"(src) : "memory");
}
#define CP_COMMIT() asm volatile("cp.async.commit_group;" ::: "memory")
#define CP_WAIT(n)  asm volatile("cp.async.wait_group %0;" :: "n"(n) : "memory")

// ---------------------------------------------------------------------------
// K1a: partial conv1 over half the C range (split-K = 2). (round-8, unchanged)
// ---------------------------------------------------------------------------
__global__ __launch_bounds__(128) void k1a_partial(
        const float* __restrict__ x,
        const float* __restrict__ w1w) {
    __shared__ float As[64 * 68];    // [k][o]
    __shared__ float Bs[64 * 32];    // [k][px]

    const int tid = threadIdx.x;
    const int tx = tid & 7;
    const int ty = tid >> 3;
    const int px0 = blockIdx.x * 32;
    const int b = blockIdx.y;
    const int ks = blockIdx.z;

    float acc[4][4];
#pragma unroll
    for (int i = 0; i < 4; ++i)
#pragma unroll
        for (int u = 0; u < 4; ++u) acc[i][u] = 0.f;

    for (int kt = ks * 128; kt < ks * 128 + 128; kt += 64) {
        {
            int k = tid & 63;
            int oh = tid >> 6;
#pragma unroll
            for (int r = 0; r < 32; ++r) {
                int o = 2 * r + oh;
                As[k * 68 + o] = w1w[o * CC + kt + k];
            }
        }
        {
            int j = tid & 31;
            int kh = tid >> 5;
#pragma unroll
            for (int r = 0; r < 16; ++r) {
                int k = 4 * r + kh;
                Bs[k * 32 + j] = x[(size_t)(b * CC + kt + k) * HW + px0 + j];
            }
        }
        __syncthreads();

#pragma unroll 16
        for (int k = 0; k < 64; ++k) {
            float4 av = *(const float4*)&As[k * 68 + ty * 4];
            float4 bv = *(const float4*)&Bs[k * 32 + tx * 4];
            acc[0][0] = fmaf(av.x, bv.x, acc[0][0]);
            acc[0][1] = fmaf(av.x, bv.y, acc[0][1]);
            acc[0][2] = fmaf(av.x, bv.z, acc[0][2]);
            acc[0][3] = fmaf(av.x, bv.w, acc[0][3]);
            acc[1][0] = fmaf(av.y, bv.x, acc[1][0]);
            acc[1][1] = fmaf(av.y, bv.y, acc[1][1]);
            acc[1][2] = fmaf(av.y, bv.z, acc[1][2]);
            acc[1][3] = fmaf(av.y, bv.w, acc[1][3]);
            acc[2][0] = fmaf(av.z, bv.x, acc[2][0]);
            acc[2][1] = fmaf(av.z, bv.y, acc[2][1]);
            acc[2][2] = fmaf(av.z, bv.z, acc[2][2]);
            acc[2][3] = fmaf(av.z, bv.w, acc[2][3]);
            acc[3][0] = fmaf(av.w, bv.x, acc[3][0]);
            acc[3][1] = fmaf(av.w, bv.y, acc[3][1]);
            acc[3][2] = fmaf(av.w, bv.z, acc[3][2]);
            acc[3][3] = fmaf(av.w, bv.w, acc[3][3]);
        }
        __syncthreads();
    }

#pragma unroll
    for (int i = 0; i < 4; ++i) {
        int o = ty * 4 + i;
        float4 v = make_float4(acc[i][0], acc[i][1], acc[i][2], acc[i][3]);
        *(float4*)(g_p + (size_t)ks * N1 + (size_t)(b * CR + o) * HW
                   + px0 + tx * 4) = v;
    }
}

// ---------------------------------------------------------------------------
// K1b: sum partials + BN(eval) + ReLU. (round-8, unchanged)
// ---------------------------------------------------------------------------
__global__ __launch_bounds__(256) void k1b_bn_relu(
        const float* __restrict__ gamma,
        const float* __restrict__ beta,
        const float* __restrict__ mean,
        const float* __restrict__ var) {
    int i4 = blockIdx.x * blockDim.x + threadIdx.x;
    if (i4 >= N1 / 4) return;
    int idx = i4 * 4;
    int o = (idx / HW) % CR;

    float sc = gamma[o] * rsqrtf(var[o] + 1e-5f);
    float sh = beta[o] - mean[o] * sc;

    float4 p0 = *(const float4*)(g_p + idx);
    float4 p1 = *(const float4*)(g_p + N1 + idx);
    float4 v;
    v.x = fmaxf(fmaf(p0.x + p1.x, sc, sh), 0.f);
    v.y = fmaxf(fmaf(p0.y + p1.y, sc, sh), 0.f);
    v.z = fmaxf(fmaf(p0.z + p1.z, sc, sh), 0.f);
    v.w = fmaxf(fmaf(p0.w + p1.w, sc, sh), 0.f);
    *(float4*)(g_w1 + idx) = v;
}

// ---------------------------------------------------------------------------
// K2: w2 = conv2_1x1(w1) + bias. Tile 64o x 64px, 128 thr, 8x4. (round-8)
// ---------------------------------------------------------------------------
__global__ __launch_bounds__(128) void k2_conv2(
        const float* __restrict__ w2w,
        const float* __restrict__ w2b) {
    __shared__ float As[64 * 68];
    __shared__ float Bs[64 * 64];

    const int tid = threadIdx.x;
    const int tx = tid & 15;
    const int ty = tid >> 4;
    const int px0 = blockIdx.x * 64;
    const int o0 = blockIdx.y * 64;
    const int b = blockIdx.z;

    {
        int k = tid & 63;
        int oh = tid >> 6;
#pragma unroll
        for (int r = 0; r < 32; ++r) {
            int o = 2 * r + oh;
            As[k * 68 + o] = (o0 + o < M2) ? w2w[(o0 + o) * CR + k] : 0.f;
        }
    }
    {
        int j = tid & 63;
        int kh = tid >> 6;
#pragma unroll
        for (int r = 0; r < 32; ++r) {
            int k = 2 * r + kh;
            Bs[k * 64 + j] = g_w1[(size_t)(b * CR + k) * HW + px0 + j];
        }
    }
    __syncthreads();

    float acc[8][4];
#pragma unroll
    for (int i = 0; i < 8; ++i)
#pragma unroll
        for (int u = 0; u < 4; ++u) acc[i][u] = 0.f;

#pragma unroll 8
    for (int k = 0; k < 64; ++k) {
        float4 a0 = *(const float4*)&As[k * 68 + ty * 8];
        float4 a1 = *(const float4*)&As[k * 68 + ty * 8 + 4];
        float4 bv = *(const float4*)&Bs[k * 64 + tx * 4];
        float av[8] = {a0.x, a0.y, a0.z, a0.w, a1.x, a1.y, a1.z, a1.w};
#pragma unroll
        for (int i = 0; i < 8; ++i) {
            acc[i][0] = fmaf(av[i], bv.x, acc[i][0]);
            acc[i][1] = fmaf(av[i], bv.y, acc[i][1]);
            acc[i][2] = fmaf(av[i], bv.z, acc[i][2]);
            acc[i][3] = fmaf(av[i], bv.w, acc[i][3]);
        }
    }

#pragma unroll
    for (int i = 0; i < 8; ++i) {
        int o = o0 + ty * 8 + i;
        if (o >= M2) continue;
        float bias = w2b[o];
        float4 v;
        v.x = acc[i][0] + bias;
        v.y = acc[i][1] + bias;
        v.z = acc[i][2] + bias;
        v.w = acc[i][3] + bias;
        *(float4*)(g_w2 + (size_t)(b * M2 + o) * HW + px0 + tx * 4) = v;
    }
}

// ---------------------------------------------------------------------------
// K3: involution reduce. Block = (4-row band, group, batch); 224 threads.
// Thread = 4 px x 4 ch. Weights double-buffered into smem via cp.async,
// one 7-tap row (6.3KB) per ki stage, overlapped with the previous row's
// compute. Regs drop (no weight regfile) -> 4 blocks/SM.
// ---------------------------------------------------------------------------
__global__ __launch_bounds__(224) void k3_involution(
        const float* __restrict__ x,
        float* __restrict__ out) {
    extern __shared__ float smf[];
    float* xs = smf;                              // [16ch][10rows][64]
    float* ws = smf + XS_FLOATS;                  // [2][7 taps][224 px]

    const int tid = threadIdx.x;
    const int h0 = blockIdx.x * 4;
    const int g = blockIdx.y;
    const int b = blockIdx.z;

    const float* wsrc = g_w2 + ((size_t)(b * GG + g) * K2T) * HW + h0 * WW;

    // issue weight stage for ki = 0 (7 taps x 224 floats, contiguous per tap)
    {
        uint32_t wdst = smem_u32(ws);
        for (int i = tid; i < KK * 56; i += 224) {
            int tap = i / 56;
            int j = i - tap * 56;
            cp_async16(wdst + (uint32_t)(tap * 224 + j * 4) * 4,
                       wsrc + (size_t)tap * HW + j * 4);
        }
        CP_COMMIT();
    }

    // stage x: rows h0-3 .. h0+6, cols -3..60 (clipped)
    const float* xg = x + (size_t)(b * CC + g * GC) * HW;
    for (int i = tid; i < XS_FLOATS; i += 224) {
        int ch = i / 640;
        int rem = i - ch * 640;
        int rr = rem >> 6;
        int c = rem & 63;
        int hh = h0 - 3 + rr;
        int ww = c - 3;
        float v = 0.f;
        if (hh >= 0 && hh < HH && ww >= 0 && ww < WW)
            v = xg[(size_t)ch * HW + hh * WW + ww];
        xs[i] = v;
    }

    const int q = tid % 14;
    const int cg = (tid / 14) & 3;
    const int r = tid / 56;
    const int w0 = q * 4;

    float acc[4][4];
#pragma unroll
    for (int c = 0; c < 4; ++c)
#pragma unroll
        for (int p = 0; p < 4; ++p) acc[c][p] = 0.f;

#pragma unroll
    for (int ki = 0; ki < KK; ++ki) {
        __syncthreads();   // all threads done reading buf[(ki+1)&1] (from ki-1)
        if (ki + 1 < KK) { // issue next row while current one drains/computes
            uint32_t wdst = smem_u32(ws + ((ki + 1) & 1) * WROW_FLOATS);
            for (int i = tid; i < KK * 56; i += 224) {
                int tap = i / 56;
                int j = i - tap * 56;
                cp_async16(wdst + (uint32_t)(tap * 224 + j * 4) * 4,
                           wsrc + (size_t)((ki + 1) * KK + tap) * HW + j * 4);
            }
            CP_COMMIT();
            CP_WAIT(1);    // current row (group ki) complete; next may fly
        } else {
            CP_WAIT(0);    // last row: drain fully
        }
        __syncthreads();   // current row visible to all threads

        const float* wrow = ws + (ki & 1) * WROW_FLOATS + r * 56 + w0;
        float4 wv[7];
#pragma unroll
        for (int kj = 0; kj < KK; ++kj)
            wv[kj] = *(const float4*)(wrow + kj * 224);
#pragma unroll
        for (int c = 0; c < 4; ++c) {
            const float* xr = &xs[(cg * 4 + c) * 640 + (r + ki) * 64 + w0];
            float4 xa = *(const float4*)(xr);
            float4 xb = *(const float4*)(xr + 4);
            float4 xc = *(const float4*)(xr + 8);
            float xw[12] = {xa.x, xa.y, xa.z, xa.w,
                            xb.x, xb.y, xb.z, xb.w,
                            xc.x, xc.y, xc.z, xc.w};
#pragma unroll
            for (int kj = 0; kj < KK; ++kj) {
                acc[c][0] = fmaf(wv[kj].x, xw[kj + 0], acc[c][0]);
                acc[c][1] = fmaf(wv[kj].y, xw[kj + 1], acc[c][1]);
                acc[c][2] = fmaf(wv[kj].z, xw[kj + 2], acc[c][2]);
                acc[c][3] = fmaf(wv[kj].w, xw[kj + 3], acc[c][3]);
            }
        }
    }

    const int h = h0 + r;
#pragma unroll
    for (int c = 0; c < 4; ++c) {
        float4 v = make_float4(acc[c][0], acc[c][1], acc[c][2], acc[c][3]);
        *(float4*)(out + (size_t)(b * CC + g * GC + cg * 4 + c) * HW
                   + h * WW + w0) = v;
    }
}

// ---------------------------------------------------------------------------
extern "C" void kernel_launch(void* const* d_in, const int* in_sizes, int n_in,
                              void* d_out, int out_size) {
    const float* x     = (const float*)d_in[0];
    const float* w1w   = (const float*)d_in[1];
    const float* gamma = (const float*)d_in[2];
    const float* beta  = (const float*)d_in[3];
    const float* mean  = (const float*)d_in[4];
    const float* var   = (const float*)d_in[5];
    const float* w2w   = (const float*)d_in[6];
    const float* w2b   = (const float*)d_in[7];
    float* out = (float*)d_out;

    static bool attr_set = false;
    if (!attr_set) {
        cudaFuncSetAttribute(k3_involution,
                             cudaFuncAttributeMaxDynamicSharedMemorySize,
                             K3_SMEM_BYTES);
        attr_set = true;
    }

    dim3 g1(HW / 32, BB, 2);                    // 98 x 4 x 2 = 784
    k1a_partial<<<g1, 128>>>(x, w1w);

    k1b_bn_relu<<<(N1 / 4 + 255) / 256, 256>>>(gamma, beta, mean, var);

    dim3 g2(HW / 64, (M2 + 63) / 64, BB);       // 49 x 13 x 4 = 2548
    k2_conv2<<<g2, 128>>>(w2w, w2b);

    dim3 g3(HH / 4, GG, BB);                    // 14 x 16 x 4 = 896
    k3_involution<<<g3, 224, K3_SMEM_BYTES>>>(x, out);
}